// round 14
// baseline (speedup 1.0000x reference)
#include <cuda_runtime.h>
#include <cuda_fp16.h>
#include <math.h>
#include <stdint.h>

#define NN   20000
#define NN_PAD 20480
#define TT   256
#define EE   320000
#define GG   64
#define CTC  8
#define CPC  16
#define EMB  768
#define FIN  512
#define BN_EPS 1e-5f

// ---------------- scratch (no allocations allowed) ----------------
__device__ float g_h0[(size_t)NN * FIN];     // half view: conv output
__device__ float g_agg[(size_t)NN * EMB];    // half view: gather output
__device__ float g_z[(size_t)NN * EMB];      // half view: gin hidden
__device__ float g_h1[(size_t)NN * EMB];     // half view h1; later float h2
__device__ float g_wt1[EMB * FIN];           // half view: w^T
__device__ float g_wt2[EMB * EMB];
__device__ float g_wt3[EMB * EMB];
__device__ float g_wt4[EMB * EMB];
__device__ int   g_deg[NN_PAD];
__device__ int   g_off[NN + 1];
__device__ int   g_srcs[EE];

// ---------------- helpers ----------------
__device__ __forceinline__ uint32_t smem_u32(const void* p) {
    uint32_t a;
    asm("{ .reg .u64 t; cvta.to.shared.u64 t, %1; cvt.u32.u64 %0, t; }" : "=r"(a) : "l"(p));
    return a;
}
__device__ __forceinline__ uint32_t pack_h2(float x, float y) {
    __half2 h = __floats2half2_rn(x, y);
    return *(uint32_t*)&h;
}
__device__ __forceinline__ float2 unpack_h2(uint32_t u) {
    __half2 h = *(__half2*)&u;
    return __half22float2(h);
}
__device__ __forceinline__ void mma_f16(float* c, const uint32_t* a, uint32_t b0, uint32_t b1) {
    asm volatile("mma.sync.aligned.m16n8k16.row.col.f32.f16.f16.f32 "
        "{%0,%1,%2,%3}, {%4,%5,%6,%7}, {%8,%9}, {%0,%1,%2,%3};"
        : "+f"(c[0]), "+f"(c[1]), "+f"(c[2]), "+f"(c[3])
        : "r"(a[0]), "r"(a[1]), "r"(a[2]), "r"(a[3]), "r"(b0), "r"(b1));
}
#define LDSM4(d, addr) \
    asm volatile("ldmatrix.sync.aligned.m8n8.x4.shared.b16 {%0,%1,%2,%3}, [%4];" \
        : "=r"((d)[0]), "=r"((d)[1]), "=r"((d)[2]), "=r"((d)[3]) : "r"(addr))

// ---------------- weight transposes (fp16 output), all four in one launch ----------------
__global__ void transpose_all_kernel(const float* __restrict__ w1, const float* __restrict__ w2,
                                     const float* __restrict__ w3, const float* __restrict__ w4,
                                     __half* __restrict__ t1, __half* __restrict__ t2,
                                     __half* __restrict__ t3, __half* __restrict__ t4)
{
    const int which = blockIdx.z;
    const float* W; __half* Wt; int K;
    if (which == 0)      { W = w1; Wt = t1; K = FIN; }
    else if (which == 1) { W = w2; Wt = t2; K = EMB; }
    else if (which == 2) { W = w3; Wt = t3; K = EMB; }
    else                 { W = w4; Wt = t4; K = EMB; }
    const int kb = blockIdx.x * 32, nb = blockIdx.y * 32;
    if (kb >= K) return;
    __shared__ float tile[32][33];
    const int tx = threadIdx.x, ty = threadIdx.y;  // 32 x 8
    #pragma unroll
    for (int i = ty; i < 32; i += 8)
        tile[i][tx] = W[(size_t)(kb + i) * EMB + nb + tx];
    __syncthreads();
    #pragma unroll
    for (int i = ty; i < 32; i += 8)
        Wt[(size_t)(nb + i) * K + kb + tx] = __float2half_rn(tile[tx][i]);
}

// ---------------- edge sort: histogram -> scan -> fill ----------------
__global__ void zero_deg_kernel(int* __restrict__ deg) {
    int i = blockIdx.x * 256 + threadIdx.x;
    if (i < NN_PAD) deg[i] = 0;
}
__global__ void hist_kernel(const int* __restrict__ ei, int* __restrict__ deg) {
    int e = blockIdx.x * 256 + threadIdx.x;
    if (e < EE) atomicAdd(&deg[ei[EE + e]], 1);
}
#define SCAN_ITEMS 20
__global__ __launch_bounds__(1024)
void scan_kernel(int* __restrict__ deg, int* __restrict__ off) {
    __shared__ int wsum[32];
    const int tid = threadIdx.x;
    const int lane = tid & 31, w = tid >> 5;
    const int base = tid * SCAN_ITEMS;
    int vals[SCAN_ITEMS];
    const int4* d4 = (const int4*)deg;
    #pragma unroll
    for (int j = 0; j < 5; j++) {
        const int4 v = d4[tid * 5 + j];
        vals[4 * j + 0] = v.x; vals[4 * j + 1] = v.y;
        vals[4 * j + 2] = v.z; vals[4 * j + 3] = v.w;
    }
    int loc[SCAN_ITEMS];
    int s = 0;
    #pragma unroll
    for (int j = 0; j < SCAN_ITEMS; j++) { loc[j] = s; s += vals[j]; }
    int x = s;
    #pragma unroll
    for (int d = 1; d < 32; d <<= 1) { int y = __shfl_up_sync(~0u, x, d); if (lane >= d) x += y; }
    if (lane == 31) wsum[w] = x;
    __syncthreads();
    if (w == 0) {
        int t = wsum[lane];
        #pragma unroll
        for (int d = 1; d < 32; d <<= 1) { int y = __shfl_up_sync(~0u, t, d); if (lane >= d) t += y; }
        wsum[lane] = t;
    }
    __syncthreads();
    const int excl = (x - s) + ((w == 0) ? 0 : wsum[w - 1]);
    #pragma unroll
    for (int j = 0; j < SCAN_ITEMS; j++) {
        const int i = base + j;
        if (i < NN) { off[i] = excl + loc[j]; deg[i] = 0; }
    }
    if (tid == 0) off[NN] = EE;
}
__global__ void fill_kernel(const int* __restrict__ ei, const int* __restrict__ off,
                            int* __restrict__ cursor, int* __restrict__ srcs) {
    int e = blockIdx.x * 256 + threadIdx.x;
    if (e >= EE) return;
    const int d = ei[EE + e];
    const int p = off[d] + atomicAdd(&cursor[d], 1);
    srcs[p] = ei[e];
}

// ---------------- gather (fp16): agg[n] = h[n] + sum h[src], fp32 accumulate ----------------
template <int F>
__global__ void gather_kernel(const __half* __restrict__ h, const int* __restrict__ off,
                              const int* __restrict__ srcs, __half* __restrict__ agg)
{
    const int n = blockIdx.x;
    const int tid = threadIdx.x;           // F/8 threads, one uint4 (8 halves) each
    const int stride = F / 8;
    const uint4* hv = (const uint4*)h;
    float a[8];
    {
        const uint4 u = hv[(size_t)n * stride + tid];
        float2 f;
        f = unpack_h2(u.x); a[0] = f.x; a[1] = f.y;
        f = unpack_h2(u.y); a[2] = f.x; a[3] = f.y;
        f = unpack_h2(u.z); a[4] = f.x; a[5] = f.y;
        f = unpack_h2(u.w); a[6] = f.x; a[7] = f.y;
    }
    const int lo = off[n], hi = off[n + 1];
    int r = lo;
    for (; r + 4 <= hi; r += 4) {
        uint4 v[4];
        #pragma unroll
        for (int j = 0; j < 4; j++)
            v[j] = hv[(size_t)__ldg(&srcs[r + j]) * stride + tid];
        #pragma unroll
        for (int j = 0; j < 4; j++) {
            float2 f;
            f = unpack_h2(v[j].x); a[0] += f.x; a[1] += f.y;
            f = unpack_h2(v[j].y); a[2] += f.x; a[3] += f.y;
            f = unpack_h2(v[j].z); a[4] += f.x; a[5] += f.y;
            f = unpack_h2(v[j].w); a[6] += f.x; a[7] += f.y;
        }
    }
    for (; r < hi; r++) {
        const uint4 u = hv[(size_t)srcs[r] * stride + tid];
        float2 f;
        f = unpack_h2(u.x); a[0] += f.x; a[1] += f.y;
        f = unpack_h2(u.y); a[2] += f.x; a[3] += f.y;
        f = unpack_h2(u.z); a[4] += f.x; a[5] += f.y;
        f = unpack_h2(u.w); a[6] += f.x; a[7] += f.y;
    }
    uint4 o;
    o.x = pack_h2(a[0], a[1]); o.y = pack_h2(a[2], a[3]);
    o.z = pack_h2(a[4], a[5]); o.w = pack_h2(a[6], a[7]);
    ((uint4*)agg)[(size_t)n * stride + tid] = o;
}

// ---------------- temporal conv stack: warp-per-channel depthwise, fp16 output ----------------
#define ROWY 280   // y0 row stride (floats), left halo 12
#define ROWC 264   // yc row stride (floats)
__global__ __launch_bounds__(256)
void conv_kernel(const float* __restrict__ x,
                 const float* __restrict__ w0,
                 const float* __restrict__ g0, const float* __restrict__ b0,
                 const float* __restrict__ m0, const float* __restrict__ v0,
                 const float* __restrict__ w1,
                 const float* __restrict__ w2,
                 const float* __restrict__ g2, const float* __restrict__ b2,
                 const float* __restrict__ m2, const float* __restrict__ v2,
                 __half* __restrict__ h0out)
{
    const int n = blockIdx.x;
    const int t = threadIdx.x;       // 256 = TT

    __shared__ float sx[TT + 32];
    __shared__ float sy2[CTC * ROWY];   // [ch][time+halo12]
    __shared__ float yc2[CTC * ROWC];   // [ch][time]
    __shared__ float sw0[33 * CTC];
    __shared__ float sw1[21 * CTC];
    __shared__ float sw2[CTC * CPC];
    __shared__ float bn0s[CTC], bn0t[CTC], bn2s[CPC], bn2t[CPC];

    sx[16 + t] = x[(size_t)n * TT + t];
    if (t < 16) { sx[t] = 0.f; sx[16 + TT + t] = 0.f; }
    for (int i = t; i < 33 * CTC; i += 256) sw0[i] = w0[i];
    for (int i = t; i < 21 * CTC; i += 256) sw1[i] = w1[i];
    for (int i = t; i < CTC * CPC; i += 256) sw2[i] = w2[i];
    if (t < CTC) { float s = g0[t] * rsqrtf(v0[t] + BN_EPS); bn0s[t] = s; bn0t[t] = b0[t] - m0[t] * s; }
    if (t < CPC) { float s = g2[t] * rsqrtf(v2[t] + BN_EPS); bn2s[t] = s; bn2t[t] = b2[t] - m2[t] * s; }
    __syncthreads();

    // conv0 (per-time thread) + BN0 -> transposed smem [ch][12 + t]
    {
        float4 ya = make_float4(0.f, 0.f, 0.f, 0.f);
        float4 yb = make_float4(0.f, 0.f, 0.f, 0.f);
        #pragma unroll
        for (int k = 0; k < 33; k++) {
            const float xv = sx[t + k];
            const float4 wa = *(const float4*)&sw0[k * CTC];
            const float4 wb = *(const float4*)&sw0[k * CTC + 4];
            ya.x = fmaf(xv, wa.x, ya.x); ya.y = fmaf(xv, wa.y, ya.y);
            ya.z = fmaf(xv, wa.z, ya.z); ya.w = fmaf(xv, wa.w, ya.w);
            yb.x = fmaf(xv, wb.x, yb.x); yb.y = fmaf(xv, wb.y, yb.y);
            yb.z = fmaf(xv, wb.z, yb.z); yb.w = fmaf(xv, wb.w, yb.w);
        }
        const float4 sa = *(const float4*)&bn0s[0], ta = *(const float4*)&bn0t[0];
        const float4 sb = *(const float4*)&bn0s[4], tb = *(const float4*)&bn0t[4];
        float y0[CTC];
        y0[0] = fmaf(ya.x, sa.x, ta.x); y0[1] = fmaf(ya.y, sa.y, ta.y);
        y0[2] = fmaf(ya.z, sa.z, ta.z); y0[3] = fmaf(ya.w, sa.w, ta.w);
        y0[4] = fmaf(yb.x, sb.x, tb.x); y0[5] = fmaf(yb.y, sb.y, tb.y);
        y0[6] = fmaf(yb.z, sb.z, tb.z); y0[7] = fmaf(yb.w, sb.w, tb.w);
        #pragma unroll
        for (int c = 0; c < CTC; c++) sy2[c * ROWY + 12 + t] = y0[c];
        if (t < 12) {
            #pragma unroll
            for (int c = 0; c < CTC; c++) { sy2[c * ROWY + t] = 0.f; sy2[c * ROWY + 268 + t] = 0.f; }
        }
    }
    __syncthreads();

    // depthwise conv1: warp = channel, lane = 8-output block; sliding register window
    {
        const int ch = t >> 5, tb = t & 31;
        float regy[32];
        const float* row = &sy2[ch * ROWY + 8 * tb];
        #pragma unroll
        for (int i = 0; i < 8; i++)
            *(float4*)&regy[4 * i] = *(const float4*)&row[4 * i];
        float o[8];
        #pragma unroll
        for (int j = 0; j < 8; j++) o[j] = 0.f;
        #pragma unroll
        for (int k = 0; k < 21; k++) {
            const float wv = sw1[k * CTC + ch];
            #pragma unroll
            for (int j = 0; j < 8; j++)
                o[j] = fmaf(regy[j + k + 2], wv, o[j]);
        }
        float4 s0, s1;
        s0.x = fmaxf(o[0], 0.f); s0.y = fmaxf(o[1], 0.f);
        s0.z = fmaxf(o[2], 0.f); s0.w = fmaxf(o[3], 0.f);
        s1.x = fmaxf(o[4], 0.f); s1.y = fmaxf(o[5], 0.f);
        s1.z = fmaxf(o[6], 0.f); s1.w = fmaxf(o[7], 0.f);
        *(float4*)&yc2[ch * ROWC + 8 * tb]     = s0;
        *(float4*)&yc2[ch * ROWC + 8 * tb + 4] = s1;
    }
    __syncthreads();

    // pointwise conv2 + BN2 + relu + pool (per-time thread)
    float yc[CTC];
    #pragma unroll
    for (int c = 0; c < CTC; c++) yc[c] = yc2[c * ROWC + t];

    float4 yp4[4];
    #pragma unroll
    for (int j = 0; j < 4; j++) yp4[j] = make_float4(0.f, 0.f, 0.f, 0.f);
    #pragma unroll
    for (int c = 0; c < CTC; c++) {
        const float a = yc[c];
        #pragma unroll
        for (int j = 0; j < 4; j++) {
            const float4 w = *(const float4*)&sw2[c * CPC + j * 4];
            yp4[j].x = fmaf(a, w.x, yp4[j].x); yp4[j].y = fmaf(a, w.y, yp4[j].y);
            yp4[j].z = fmaf(a, w.z, yp4[j].z); yp4[j].w = fmaf(a, w.w, yp4[j].w);
        }
    }
    float yp[CPC];
    #pragma unroll
    for (int j = 0; j < 4; j++) {
        const float4 s4 = *(const float4*)&bn2s[j * 4];
        const float4 t4 = *(const float4*)&bn2t[j * 4];
        yp[j * 4 + 0] = fmaxf(fmaf(yp4[j].x, s4.x, t4.x), 0.f);
        yp[j * 4 + 1] = fmaxf(fmaf(yp4[j].y, s4.y, t4.y), 0.f);
        yp[j * 4 + 2] = fmaxf(fmaf(yp4[j].z, s4.z, t4.z), 0.f);
        yp[j * 4 + 3] = fmaxf(fmaf(yp4[j].w, s4.w, t4.w), 0.f);
    }

    #pragma unroll
    for (int p = 0; p < CPC; p++) {
        float v = yp[p];
        v += __shfl_xor_sync(0xffffffffu, v, 1);
        v += __shfl_xor_sync(0xffffffffu, v, 2);
        v += __shfl_xor_sync(0xffffffffu, v, 4);
        yp[p] = v * 0.125f;
    }
    if ((t & 7) == 0) {
        const int tp = t >> 3;
        __half* dst = h0out + (size_t)n * FIN + tp * CPC;
        uint4 o0, o1;
        o0.x = pack_h2(yp[0],  yp[1]);  o0.y = pack_h2(yp[2],  yp[3]);
        o0.z = pack_h2(yp[4],  yp[5]);  o0.w = pack_h2(yp[6],  yp[7]);
        o1.x = pack_h2(yp[8],  yp[9]);  o1.y = pack_h2(yp[10], yp[11]);
        o1.z = pack_h2(yp[12], yp[13]); o1.w = pack_h2(yp[14], yp[15]);
        *(uint4*)dst = o0;
        *(uint4*)(dst + 8) = o1;
    }
}

// ---------------- fp16 mma GEMM: C = relu(A @ Bt^T + bias) ----------------
// BM=128, BN=256, BK=64 halves. 8 warps as 2x4, warp tile 64x64, ldmatrix frags
// with register double-buffering. Guard-specialized paths. 3-stage cp.async.cg.
#define BM 128
#define BN 256
#define ROWB 144
#define STAGEB ((BM + BN) * ROWB)
#define GEMM_SMEM (3 * STAGEB)

#define LDSM_SET(a, b, abase_, bbase_, ks_) do { \
    _Pragma("unroll") \
    for (int fm = 0; fm < 4; fm++) \
        LDSM4((a)[fm], (abase_) + fm * (16 * ROWB) + (ks_) * 32); \
    _Pragma("unroll") \
    for (int fp = 0; fp < 4; fp++) \
        LDSM4((b)[fp], (bbase_) + fp * (16 * ROWB) + (ks_) * 32); \
} while (0)

#define MMAS(a, b) do { \
    _Pragma("unroll") \
    for (int fm = 0; fm < 4; fm++) \
        _Pragma("unroll") \
        for (int fn = 0; fn < 8; fn++) \
            mma_f16(acc[fm][fn], (a)[fm], (b)[fn >> 1][(fn & 1) * 2], (b)[fn >> 1][(fn & 1) * 2 + 1]); \
} while (0)

template <bool FP32OUT>
__global__ __launch_bounds__(256, 1)
void gemm_mma(const __half* __restrict__ A, const __half* __restrict__ Bt,
              const float* __restrict__ bias, void* __restrict__ Cout,
              int M, int K, int N)
{
    extern __shared__ char smc[];
    const uint32_t sbase = smem_u32(smc);
    const int tid = threadIdx.x;
    const int wid = tid >> 5, lane = tid & 31;
    const int g = lane >> 2, tq = lane & 3;
    const int wm = wid >> 2, wn = wid & 3;
    const int row0 = blockIdx.y * BM;
    const int col0 = blockIdx.x * BN;
    const bool guard = (row0 + BM > M);

    const int lm = lane >> 3, lr = lane & 7;
    const uint32_t aoff = (uint32_t)((wm * 64 + (lm & 1) * 8 + lr) * ROWB + ((lm >> 1) * 8) * 2);
    const uint32_t boff = (uint32_t)(BM * ROWB + (wn * 64 + (lm >> 1) * 8 + lr) * ROWB + ((lm & 1) * 8) * 2);

    float acc[4][8][4];
    #pragma unroll
    for (int i = 0; i < 4; i++)
        #pragma unroll
        for (int j = 0; j < 8; j++)
            #pragma unroll
            for (int r = 0; r < 4; r++) acc[i][j][r] = 0.f;

    const int nchunk = K >> 6;

    auto issue = [&](int c) {
        const uint32_t st = sbase + (c % 3) * STAGEB;
        const int k0 = c << 6;
        if (!guard) {
            #pragma unroll
            for (int i = 0; i < 4; i++) {
                const int seg = tid + i * 256;
                const int r = seg >> 3, c8 = seg & 7;
                const uint32_t da = st + r * ROWB + c8 * 16;
                const __half* sa = A + (size_t)(row0 + r) * K + k0 + c8 * 8;
                asm volatile("cp.async.cg.shared.global [%0], [%1], 16;" :: "r"(da), "l"(sa));
            }
        } else {
            #pragma unroll
            for (int i = 0; i < 4; i++) {
                const int seg = tid + i * 256;
                const int r = seg >> 3, c8 = seg & 7;
                const uint32_t da = st + r * ROWB + c8 * 16;
                const __half* sa = A + (size_t)(row0 + r) * K + k0 + c8 * 8;
                const int pn = (row0 + r < M) ? 16 : 0;
                asm volatile("cp.async.cg.shared.global [%0], [%1], 16, %2;"
                             :: "r"(da), "l"(sa), "r"(pn));
            }
        }
        #pragma unroll
        for (int i = 0; i < 8; i++) {
            const int seg = tid + i * 256;
            const int r = seg >> 3, c8 = seg & 7;
            const uint32_t db = st + BM * ROWB + r * ROWB + c8 * 16;
            const __half* sb = Bt + (size_t)(col0 + r) * K + k0 + c8 * 8;
            asm volatile("cp.async.cg.shared.global [%0], [%1], 16;" :: "r"(db), "l"(sb));
        }
        asm volatile("cp.async.commit_group;");
    };

    issue(0);
    if (nchunk > 1) issue(1);

    for (int c = 0; c < nchunk; c++) {
        if (c + 1 < nchunk) asm volatile("cp.async.wait_group 1;");
        else                asm volatile("cp.async.wait_group 0;");
        __syncthreads();
        if (c + 2 < nchunk) issue(c + 2);

        const uint32_t abase = sbase + (c % 3) * STAGEB + aoff;
        const uint32_t bbase = sbase + (c % 3) * STAGEB + boff;
        // register double-buffered fragments across ks
        uint32_t a0[4][4], b0[4][4], a1[4][4], b1[4][4];
        LDSM_SET(a0, b0, abase, bbase, 0);
        LDSM_SET(a1, b1, abase, bbase, 1);
        MMAS(a0, b0);
        LDSM_SET(a0, b0, abase, bbase, 2);
        MMAS(a1, b1);
        LDSM_SET(a1, b1, abase, bbase, 3);
        MMAS(a0, b0);
        MMAS(a1, b1);
        // no trailing barrier: next iteration's top barrier orders stage reuse
    }

    // epilogue: bias + relu (guard-specialized)
    #pragma unroll
    for (int fm = 0; fm < 4; fm++) {
        const int r0 = row0 + wm * 64 + fm * 16 + g;
        #pragma unroll
        for (int fn = 0; fn < 8; fn++) {
            const int cc = col0 + wn * 64 + fn * 8 + tq * 2;
            const float2 bv = *(const float2*)(bias + cc);
            #pragma unroll
            for (int half = 0; half < 2; half++) {
                const int rr = r0 + half * 8;
                if (!guard || rr < M) {
                    const float ox = fmaxf(acc[fm][fn][half * 2 + 0] + bv.x, 0.f);
                    const float oy = fmaxf(acc[fm][fn][half * 2 + 1] + bv.y, 0.f);
                    if (FP32OUT) {
                        float2 o; o.x = ox; o.y = oy;
                        *(float2*)((float*)Cout + (size_t)rr * N + cc) = o;
                    } else {
                        *(uint32_t*)((__half*)Cout + (size_t)rr * N + cc) = pack_h2(ox, oy);
                    }
                }
            }
        }
    }
}

// ---------------- fused per-graph mean pool + head (batch is sorted) ----------------
__device__ __forceinline__ int dev_lower_bound(const int* a, int n, int v) {
    int lo = 0, hi = n;
    while (lo < hi) { int m = (lo + hi) >> 1; if (a[m] < v) lo = m + 1; else hi = m; }
    return lo;
}

__global__ void poolhead_kernel(const float* __restrict__ h, const int* __restrict__ batch,
                                const float* __restrict__ dw, const float* __restrict__ db,
                                float* __restrict__ out)
{
    const int g = blockIdx.x;
    const int t = threadIdx.x;  // 256
    const int lo = dev_lower_bound(batch, NN, g);
    const int hi = dev_lower_bound(batch, NN, g + 1);
    float a0 = 0.f, a1 = 0.f, a2 = 0.f;
    int r = lo;
    for (; r + 2 <= hi; r += 2) {
        const float* r0 = h + (size_t)r * EMB;
        const float* r1 = h + (size_t)(r + 1) * EMB;
        a0 += r0[t] + r1[t];
        a1 += r0[t + 256] + r1[t + 256];
        a2 += r0[t + 512] + r1[t + 512];
    }
    if (r < hi) {
        const float* row = h + (size_t)r * EMB;
        a0 += row[t]; a1 += row[t + 256]; a2 += row[t + 512];
    }
    const float inv = 1.0f / fmaxf((float)(hi - lo), 1.0f);
    __shared__ float sp[EMB];
    sp[t] = a0 * inv; sp[t + 256] = a1 * inv; sp[t + 512] = a2 * inv;
    __syncthreads();

    float p0 = 0.f, p1 = 0.f, p2 = 0.f, p3 = 0.f;
    #pragma unroll
    for (int kk = t; kk < EMB; kk += 256) {
        const float pv = sp[kk];
        const float4 w = *(const float4*)(dw + kk * 4);
        p0 = fmaf(pv, w.x, p0); p1 = fmaf(pv, w.y, p1);
        p2 = fmaf(pv, w.z, p2); p3 = fmaf(pv, w.w, p3);
    }
    #pragma unroll
    for (int d = 16; d >= 1; d >>= 1) {
        p0 += __shfl_xor_sync(~0u, p0, d);
        p1 += __shfl_xor_sync(~0u, p1, d);
        p2 += __shfl_xor_sync(~0u, p2, d);
        p3 += __shfl_xor_sync(~0u, p3, d);
    }
    __shared__ float red[4][8];
    const int w8 = t >> 5;
    if ((t & 31) == 0) { red[0][w8] = p0; red[1][w8] = p1; red[2][w8] = p2; red[3][w8] = p3; }
    __syncthreads();
    if (t == 0) {
        float l[4];
        #pragma unroll
        for (int i = 0; i < 4; i++) {
            float s = 0.f;
            #pragma unroll
            for (int j = 0; j < 8; j++) s += red[i][j];
            l[i] = s + db[i];
        }
        const float m = fmaxf(fmaxf(l[0], l[1]), fmaxf(l[2], l[3]));
        const float lse = logf(expf(l[0] - m) + expf(l[1] - m) + expf(l[2] - m) + expf(l[3] - m)) + m;
        float* o = out + g * 4;
        o[0] = l[0] - lse; o[1] = l[1] - lse; o[2] = l[2] - lse; o[3] = l[3] - lse;
    }
}

// ---------------- launch ----------------
extern "C" void kernel_launch(void* const* d_in, const int* in_sizes, int n_in,
                              void* d_out, int out_size)
{
    const float* x        = (const float*)d_in[0];
    const int*   ei       = (const int*)d_in[1];
    const int*   batch    = (const int*)d_in[2];
    const float* conv0_w  = (const float*)d_in[3];
    const float* bn0_g    = (const float*)d_in[4];
    const float* bn0_b    = (const float*)d_in[5];
    const float* bn0_m    = (const float*)d_in[6];
    const float* bn0_v    = (const float*)d_in[7];
    const float* conv1_w  = (const float*)d_in[8];
    const float* conv2_w  = (const float*)d_in[9];
    const float* bn2_g    = (const float*)d_in[10];
    const float* bn2_b    = (const float*)d_in[11];
    const float* bn2_m    = (const float*)d_in[12];
    const float* bn2_v    = (const float*)d_in[13];
    const float* g1w1     = (const float*)d_in[14];
    const float* g1b1     = (const float*)d_in[15];
    const float* g1w2     = (const float*)d_in[16];
    const float* g1b2     = (const float*)d_in[17];
    const float* g2w1     = (const float*)d_in[18];
    const float* g2b1     = (const float*)d_in[19];
    const float* g2w2     = (const float*)d_in[20];
    const float* g2b2     = (const float*)d_in[21];
    const float* dense_w  = (const float*)d_in[22];
    const float* dense_b  = (const float*)d_in[23];
    float* out = (float*)d_out;

    float *h0f, *aggf, *zf, *h1f, *wt1f, *wt2f, *wt3f, *wt4f;
    int *deg, *off, *srcs;
    cudaGetSymbolAddress((void**)&h0f,    g_h0);
    cudaGetSymbolAddress((void**)&aggf,   g_agg);
    cudaGetSymbolAddress((void**)&zf,     g_z);
    cudaGetSymbolAddress((void**)&h1f,    g_h1);
    cudaGetSymbolAddress((void**)&wt1f,   g_wt1);
    cudaGetSymbolAddress((void**)&wt2f,   g_wt2);
    cudaGetSymbolAddress((void**)&wt3f,   g_wt3);
    cudaGetSymbolAddress((void**)&wt4f,   g_wt4);
    cudaGetSymbolAddress((void**)&deg,    g_deg);
    cudaGetSymbolAddress((void**)&off,    g_off);
    cudaGetSymbolAddress((void**)&srcs,   g_srcs);

    __half* h0  = (__half*)h0f;
    __half* agg = (__half*)aggf;
    __half* z   = (__half*)zf;
    __half* h1  = (__half*)h1f;
    float*  h2  = h1f;             // fp32 view for gemm4 output
    __half* wt1 = (__half*)wt1f;
    __half* wt2 = (__half*)wt2f;
    __half* wt3 = (__half*)wt3f;
    __half* wt4 = (__half*)wt4f;

    cudaFuncSetAttribute(gemm_mma<false>, cudaFuncAttributeMaxDynamicSharedMemorySize, GEMM_SMEM);
    cudaFuncSetAttribute(gemm_mma<true >, cudaFuncAttributeMaxDynamicSharedMemorySize, GEMM_SMEM);

    static cudaStream_t s_sort = nullptr, s_wt = nullptr;
    static cudaEvent_t  e_root = nullptr, e_sort = nullptr, e_wt = nullptr;
    if (!s_sort) {
        cudaStreamCreateWithFlags(&s_sort, cudaStreamNonBlocking);
        cudaStreamCreateWithFlags(&s_wt,   cudaStreamNonBlocking);
        cudaEventCreateWithFlags(&e_root, cudaEventDisableTiming);
        cudaEventCreateWithFlags(&e_sort, cudaEventDisableTiming);
        cudaEventCreateWithFlags(&e_wt,   cudaEventDisableTiming);
    }

    const dim3 ggrid(EMB / BN, (NN + BM - 1) / BM);   // (3, 157)

    cudaEventRecord(e_root, 0);
    cudaStreamWaitEvent(s_sort, e_root, 0);
    cudaStreamWaitEvent(s_wt,   e_root, 0);

    // side stream 1: edge sort chain
    zero_deg_kernel<<<(NN_PAD + 255) / 256, 256, 0, s_sort>>>(deg);
    hist_kernel<<<(EE + 255) / 256, 256, 0, s_sort>>>(ei, deg);
    scan_kernel<<<1, 1024, 0, s_sort>>>(deg, off);
    fill_kernel<<<(EE + 255) / 256, 256, 0, s_sort>>>(ei, off, deg, srcs);
    cudaEventRecord(e_sort, s_sort);

    // side stream 2: weight transposes
    transpose_all_kernel<<<dim3(EMB / 32, EMB / 32, 4), dim3(32, 8), 0, s_wt>>>(
        g1w1, g1w2, g2w1, g2w2, wt1, wt2, wt3, wt4);
    cudaEventRecord(e_wt, s_wt);

    // main stream: conv overlaps both side chains
    conv_kernel<<<NN, 256>>>(x, conv0_w, bn0_g, bn0_b, bn0_m, bn0_v,
                             conv1_w, conv2_w, bn2_g, bn2_b, bn2_m, bn2_v, h0);

    cudaStreamWaitEvent(0, e_sort, 0);
    cudaStreamWaitEvent(0, e_wt, 0);

    // GIN1
    gather_kernel<FIN><<<NN, FIN / 8>>>(h0, off, srcs, agg);
    gemm_mma<false><<<ggrid, 256, GEMM_SMEM>>>(agg, wt1, g1b1, z,  NN, FIN, EMB);
    gemm_mma<false><<<ggrid, 256, GEMM_SMEM>>>(z,   wt2, g1b2, h1, NN, EMB, EMB);
    // GIN2
    gather_kernel<EMB><<<NN, EMB / 8>>>(h1, off, srcs, agg);
    gemm_mma<false><<<ggrid, 256, GEMM_SMEM>>>(agg, wt3, g2b1, z,  NN, EMB, EMB);
    gemm_mma<true ><<<ggrid, 256, GEMM_SMEM>>>(z,   wt4, g2b2, h2, NN, EMB, EMB);
    // fused pool + head
    poolhead_kernel<<<GG, 256>>>(h2, batch, dense_w, dense_b, out);
}

// round 15
// speedup vs baseline: 1.0633x; 1.0633x over previous
#include <cuda_runtime.h>
#include <cuda_fp16.h>
#include <math.h>
#include <stdint.h>

#define NN   20000
#define NN_PAD 20480
#define TT   256
#define EE   320000
#define GG   64
#define CTC  8
#define CPC  16
#define EMB  768
#define FIN  512
#define BN_EPS 1e-5f

// ---------------- scratch (no allocations allowed) ----------------
__device__ float g_h0[(size_t)NN * FIN];     // half view: conv output
__device__ float g_agg[(size_t)NN * EMB];    // half view: gather output
__device__ float g_z[(size_t)NN * EMB];      // half view: gin hidden
__device__ float g_h1[(size_t)NN * EMB];     // half view h1; later float h2
__device__ float g_wt1[EMB * FIN];           // half view: w^T
__device__ float g_wt2[EMB * EMB];
__device__ float g_wt3[EMB * EMB];
__device__ float g_wt4[EMB * EMB];
__device__ int   g_deg[NN_PAD];
__device__ int   g_off[NN + 1];
__device__ int   g_srcs[EE];

// ---------------- helpers ----------------
__device__ __forceinline__ uint32_t smem_u32(const void* p) {
    uint32_t a;
    asm("{ .reg .u64 t; cvta.to.shared.u64 t, %1; cvt.u32.u64 %0, t; }" : "=r"(a) : "l"(p));
    return a;
}
__device__ __forceinline__ uint32_t pack_h2(float x, float y) {
    __half2 h = __floats2half2_rn(x, y);
    return *(uint32_t*)&h;
}
__device__ __forceinline__ float2 unpack_h2(uint32_t u) {
    __half2 h = *(__half2*)&u;
    return __half22float2(h);
}
__device__ __forceinline__ void mma_f16(float* c, const uint32_t* a, uint32_t b0, uint32_t b1) {
    asm volatile("mma.sync.aligned.m16n8k16.row.col.f32.f16.f16.f32 "
        "{%0,%1,%2,%3}, {%4,%5,%6,%7}, {%8,%9}, {%0,%1,%2,%3};"
        : "+f"(c[0]), "+f"(c[1]), "+f"(c[2]), "+f"(c[3])
        : "r"(a[0]), "r"(a[1]), "r"(a[2]), "r"(a[3]), "r"(b0), "r"(b1));
}
#define LDSM4(d, addr) \
    asm volatile("ldmatrix.sync.aligned.m8n8.x4.shared.b16 {%0,%1,%2,%3}, [%4];" \
        : "=r"((d)[0]), "=r"((d)[1]), "=r"((d)[2]), "=r"((d)[3]) : "r"(addr))

// ---------------- weight transposes (fp16 output), all four in one launch ----------------
__global__ void transpose_all_kernel(const float* __restrict__ w1, const float* __restrict__ w2,
                                     const float* __restrict__ w3, const float* __restrict__ w4,
                                     __half* __restrict__ t1, __half* __restrict__ t2,
                                     __half* __restrict__ t3, __half* __restrict__ t4)
{
    const int which = blockIdx.z;
    const float* W; __half* Wt; int K;
    if (which == 0)      { W = w1; Wt = t1; K = FIN; }
    else if (which == 1) { W = w2; Wt = t2; K = EMB; }
    else if (which == 2) { W = w3; Wt = t3; K = EMB; }
    else                 { W = w4; Wt = t4; K = EMB; }
    const int kb = blockIdx.x * 32, nb = blockIdx.y * 32;
    if (kb >= K) return;
    __shared__ float tile[32][33];
    const int tx = threadIdx.x, ty = threadIdx.y;  // 32 x 8
    #pragma unroll
    for (int i = ty; i < 32; i += 8)
        tile[i][tx] = W[(size_t)(kb + i) * EMB + nb + tx];
    __syncthreads();
    #pragma unroll
    for (int i = ty; i < 32; i += 8)
        Wt[(size_t)(nb + i) * K + kb + tx] = __float2half_rn(tile[tx][i]);
}

// ---------------- edge sort: histogram -> scan -> fill ----------------
__global__ void zero_deg_kernel(int* __restrict__ deg) {
    int i = blockIdx.x * 256 + threadIdx.x;
    if (i < NN_PAD) deg[i] = 0;
}
__global__ void hist_kernel(const int* __restrict__ ei, int* __restrict__ deg) {
    int e = blockIdx.x * 256 + threadIdx.x;
    if (e < EE) atomicAdd(&deg[ei[EE + e]], 1);
}
#define SCAN_ITEMS 20
__global__ __launch_bounds__(1024)
void scan_kernel(int* __restrict__ deg, int* __restrict__ off) {
    __shared__ int wsum[32];
    const int tid = threadIdx.x;
    const int lane = tid & 31, w = tid >> 5;
    const int base = tid * SCAN_ITEMS;
    int vals[SCAN_ITEMS];
    const int4* d4 = (const int4*)deg;
    #pragma unroll
    for (int j = 0; j < 5; j++) {
        const int4 v = d4[tid * 5 + j];
        vals[4 * j + 0] = v.x; vals[4 * j + 1] = v.y;
        vals[4 * j + 2] = v.z; vals[4 * j + 3] = v.w;
    }
    int loc[SCAN_ITEMS];
    int s = 0;
    #pragma unroll
    for (int j = 0; j < SCAN_ITEMS; j++) { loc[j] = s; s += vals[j]; }
    int x = s;
    #pragma unroll
    for (int d = 1; d < 32; d <<= 1) { int y = __shfl_up_sync(~0u, x, d); if (lane >= d) x += y; }
    if (lane == 31) wsum[w] = x;
    __syncthreads();
    if (w == 0) {
        int t = wsum[lane];
        #pragma unroll
        for (int d = 1; d < 32; d <<= 1) { int y = __shfl_up_sync(~0u, t, d); if (lane >= d) t += y; }
        wsum[lane] = t;
    }
    __syncthreads();
    const int excl = (x - s) + ((w == 0) ? 0 : wsum[w - 1]);
    #pragma unroll
    for (int j = 0; j < SCAN_ITEMS; j++) {
        const int i = base + j;
        if (i < NN) { off[i] = excl + loc[j]; deg[i] = 0; }
    }
    if (tid == 0) off[NN] = EE;
}
__global__ void fill_kernel(const int* __restrict__ ei, const int* __restrict__ off,
                            int* __restrict__ cursor, int* __restrict__ srcs) {
    int e = blockIdx.x * 256 + threadIdx.x;
    if (e >= EE) return;
    const int d = ei[EE + e];
    const int p = off[d] + atomicAdd(&cursor[d], 1);
    srcs[p] = ei[e];
}

// ---------------- gather (fp16): agg[n] = h[n] + sum h[src], fp32 accumulate ----------------
template <int F>
__global__ void gather_kernel(const __half* __restrict__ h, const int* __restrict__ off,
                              const int* __restrict__ srcs, __half* __restrict__ agg)
{
    const int n = blockIdx.x;
    const int tid = threadIdx.x;           // F/8 threads, one uint4 (8 halves) each
    const int stride = F / 8;
    const uint4* hv = (const uint4*)h;
    float a[8];
    {
        const uint4 u = hv[(size_t)n * stride + tid];
        float2 f;
        f = unpack_h2(u.x); a[0] = f.x; a[1] = f.y;
        f = unpack_h2(u.y); a[2] = f.x; a[3] = f.y;
        f = unpack_h2(u.z); a[4] = f.x; a[5] = f.y;
        f = unpack_h2(u.w); a[6] = f.x; a[7] = f.y;
    }
    const int lo = off[n], hi = off[n + 1];
    int r = lo;
    for (; r + 8 <= hi; r += 8) {
        uint4 v[8];
        #pragma unroll
        for (int j = 0; j < 8; j++)
            v[j] = hv[(size_t)__ldg(&srcs[r + j]) * stride + tid];
        #pragma unroll
        for (int j = 0; j < 8; j++) {
            float2 f;
            f = unpack_h2(v[j].x); a[0] += f.x; a[1] += f.y;
            f = unpack_h2(v[j].y); a[2] += f.x; a[3] += f.y;
            f = unpack_h2(v[j].z); a[4] += f.x; a[5] += f.y;
            f = unpack_h2(v[j].w); a[6] += f.x; a[7] += f.y;
        }
    }
    for (; r + 4 <= hi; r += 4) {
        uint4 v[4];
        #pragma unroll
        for (int j = 0; j < 4; j++)
            v[j] = hv[(size_t)__ldg(&srcs[r + j]) * stride + tid];
        #pragma unroll
        for (int j = 0; j < 4; j++) {
            float2 f;
            f = unpack_h2(v[j].x); a[0] += f.x; a[1] += f.y;
            f = unpack_h2(v[j].y); a[2] += f.x; a[3] += f.y;
            f = unpack_h2(v[j].z); a[4] += f.x; a[5] += f.y;
            f = unpack_h2(v[j].w); a[6] += f.x; a[7] += f.y;
        }
    }
    for (; r < hi; r++) {
        const uint4 u = hv[(size_t)srcs[r] * stride + tid];
        float2 f;
        f = unpack_h2(u.x); a[0] += f.x; a[1] += f.y;
        f = unpack_h2(u.y); a[2] += f.x; a[3] += f.y;
        f = unpack_h2(u.z); a[4] += f.x; a[5] += f.y;
        f = unpack_h2(u.w); a[6] += f.x; a[7] += f.y;
    }
    uint4 o;
    o.x = pack_h2(a[0], a[1]); o.y = pack_h2(a[2], a[3]);
    o.z = pack_h2(a[4], a[5]); o.w = pack_h2(a[6], a[7]);
    ((uint4*)agg)[(size_t)n * stride + tid] = o;
}

// ---------------- temporal conv stack: warp-per-channel depthwise, fp16 output ----------------
#define ROWY 280   // y0 row stride (floats), left halo 12
#define ROWC 264   // yc row stride (floats)
__global__ __launch_bounds__(256)
void conv_kernel(const float* __restrict__ x,
                 const float* __restrict__ w0,
                 const float* __restrict__ g0, const float* __restrict__ b0,
                 const float* __restrict__ m0, const float* __restrict__ v0,
                 const float* __restrict__ w1,
                 const float* __restrict__ w2,
                 const float* __restrict__ g2, const float* __restrict__ b2,
                 const float* __restrict__ m2, const float* __restrict__ v2,
                 __half* __restrict__ h0out)
{
    const int n = blockIdx.x;
    const int t = threadIdx.x;       // 256 = TT

    __shared__ float sx[TT + 32];
    __shared__ float sy2[CTC * ROWY];   // [ch][time+halo12]
    __shared__ float yc2[CTC * ROWC];   // [ch][time]
    __shared__ float sw0[33 * CTC];
    __shared__ float sw1[21 * CTC];
    __shared__ float sw2[CTC * CPC];
    __shared__ float bn0s[CTC], bn0t[CTC], bn2s[CPC], bn2t[CPC];

    sx[16 + t] = x[(size_t)n * TT + t];
    if (t < 16) { sx[t] = 0.f; sx[16 + TT + t] = 0.f; }
    for (int i = t; i < 33 * CTC; i += 256) sw0[i] = w0[i];
    for (int i = t; i < 21 * CTC; i += 256) sw1[i] = w1[i];
    for (int i = t; i < CTC * CPC; i += 256) sw2[i] = w2[i];
    if (t < CTC) { float s = g0[t] * rsqrtf(v0[t] + BN_EPS); bn0s[t] = s; bn0t[t] = b0[t] - m0[t] * s; }
    if (t < CPC) { float s = g2[t] * rsqrtf(v2[t] + BN_EPS); bn2s[t] = s; bn2t[t] = b2[t] - m2[t] * s; }
    __syncthreads();

    // conv0 (per-time thread) + BN0 -> transposed smem [ch][12 + t]
    {
        float4 ya = make_float4(0.f, 0.f, 0.f, 0.f);
        float4 yb = make_float4(0.f, 0.f, 0.f, 0.f);
        #pragma unroll
        for (int k = 0; k < 33; k++) {
            const float xv = sx[t + k];
            const float4 wa = *(const float4*)&sw0[k * CTC];
            const float4 wb = *(const float4*)&sw0[k * CTC + 4];
            ya.x = fmaf(xv, wa.x, ya.x); ya.y = fmaf(xv, wa.y, ya.y);
            ya.z = fmaf(xv, wa.z, ya.z); ya.w = fmaf(xv, wa.w, ya.w);
            yb.x = fmaf(xv, wb.x, yb.x); yb.y = fmaf(xv, wb.y, yb.y);
            yb.z = fmaf(xv, wb.z, yb.z); yb.w = fmaf(xv, wb.w, yb.w);
        }
        const float4 sa = *(const float4*)&bn0s[0], ta = *(const float4*)&bn0t[0];
        const float4 sb = *(const float4*)&bn0s[4], tb = *(const float4*)&bn0t[4];
        float y0[CTC];
        y0[0] = fmaf(ya.x, sa.x, ta.x); y0[1] = fmaf(ya.y, sa.y, ta.y);
        y0[2] = fmaf(ya.z, sa.z, ta.z); y0[3] = fmaf(ya.w, sa.w, ta.w);
        y0[4] = fmaf(yb.x, sb.x, tb.x); y0[5] = fmaf(yb.y, sb.y, tb.y);
        y0[6] = fmaf(yb.z, sb.z, tb.z); y0[7] = fmaf(yb.w, sb.w, tb.w);
        #pragma unroll
        for (int c = 0; c < CTC; c++) sy2[c * ROWY + 12 + t] = y0[c];
        if (t < 12) {
            #pragma unroll
            for (int c = 0; c < CTC; c++) { sy2[c * ROWY + t] = 0.f; sy2[c * ROWY + 268 + t] = 0.f; }
        }
    }
    __syncthreads();

    // depthwise conv1: warp = channel, lane = 8-output block; sliding register window
    {
        const int ch = t >> 5, tb = t & 31;
        float regy[32];
        const float* row = &sy2[ch * ROWY + 8 * tb];
        #pragma unroll
        for (int i = 0; i < 8; i++)
            *(float4*)&regy[4 * i] = *(const float4*)&row[4 * i];
        float o[8];
        #pragma unroll
        for (int j = 0; j < 8; j++) o[j] = 0.f;
        #pragma unroll
        for (int k = 0; k < 21; k++) {
            const float wv = sw1[k * CTC + ch];
            #pragma unroll
            for (int j = 0; j < 8; j++)
                o[j] = fmaf(regy[j + k + 2], wv, o[j]);
        }
        float4 s0, s1;
        s0.x = fmaxf(o[0], 0.f); s0.y = fmaxf(o[1], 0.f);
        s0.z = fmaxf(o[2], 0.f); s0.w = fmaxf(o[3], 0.f);
        s1.x = fmaxf(o[4], 0.f); s1.y = fmaxf(o[5], 0.f);
        s1.z = fmaxf(o[6], 0.f); s1.w = fmaxf(o[7], 0.f);
        *(float4*)&yc2[ch * ROWC + 8 * tb]     = s0;
        *(float4*)&yc2[ch * ROWC + 8 * tb + 4] = s1;
    }
    __syncthreads();

    // pointwise conv2 + BN2 + relu + pool (per-time thread)
    float yc[CTC];
    #pragma unroll
    for (int c = 0; c < CTC; c++) yc[c] = yc2[c * ROWC + t];

    float4 yp4[4];
    #pragma unroll
    for (int j = 0; j < 4; j++) yp4[j] = make_float4(0.f, 0.f, 0.f, 0.f);
    #pragma unroll
    for (int c = 0; c < CTC; c++) {
        const float a = yc[c];
        #pragma unroll
        for (int j = 0; j < 4; j++) {
            const float4 w = *(const float4*)&sw2[c * CPC + j * 4];
            yp4[j].x = fmaf(a, w.x, yp4[j].x); yp4[j].y = fmaf(a, w.y, yp4[j].y);
            yp4[j].z = fmaf(a, w.z, yp4[j].z); yp4[j].w = fmaf(a, w.w, yp4[j].w);
        }
    }
    float yp[CPC];
    #pragma unroll
    for (int j = 0; j < 4; j++) {
        const float4 s4 = *(const float4*)&bn2s[j * 4];
        const float4 t4 = *(const float4*)&bn2t[j * 4];
        yp[j * 4 + 0] = fmaxf(fmaf(yp4[j].x, s4.x, t4.x), 0.f);
        yp[j * 4 + 1] = fmaxf(fmaf(yp4[j].y, s4.y, t4.y), 0.f);
        yp[j * 4 + 2] = fmaxf(fmaf(yp4[j].z, s4.z, t4.z), 0.f);
        yp[j * 4 + 3] = fmaxf(fmaf(yp4[j].w, s4.w, t4.w), 0.f);
    }

    #pragma unroll
    for (int p = 0; p < CPC; p++) {
        float v = yp[p];
        v += __shfl_xor_sync(0xffffffffu, v, 1);
        v += __shfl_xor_sync(0xffffffffu, v, 2);
        v += __shfl_xor_sync(0xffffffffu, v, 4);
        yp[p] = v * 0.125f;
    }
    if ((t & 7) == 0) {
        const int tp = t >> 3;
        __half* dst = h0out + (size_t)n * FIN + tp * CPC;
        uint4 o0, o1;
        o0.x = pack_h2(yp[0],  yp[1]);  o0.y = pack_h2(yp[2],  yp[3]);
        o0.z = pack_h2(yp[4],  yp[5]);  o0.w = pack_h2(yp[6],  yp[7]);
        o1.x = pack_h2(yp[8],  yp[9]);  o1.y = pack_h2(yp[10], yp[11]);
        o1.z = pack_h2(yp[12], yp[13]); o1.w = pack_h2(yp[14], yp[15]);
        *(uint4*)dst = o0;
        *(uint4*)(dst + 8) = o1;
    }
}

// ---------------- fp16 mma GEMM: C = relu(A @ Bt^T + bias) ----------------
// BM=128, BN=256, BK=64 halves. 8 warps as 2x4, warp tile 64x64, ldmatrix frags.
// 3-stage cp.async pipeline, one barrier per chunk, 1 CTA/SM.  (R12 mainloop.)
#define BM 128
#define BN 256
#define ROWB 144
#define STAGEB ((BM + BN) * ROWB)
#define GEMM_SMEM (3 * STAGEB)

template <bool FP32OUT>
__global__ __launch_bounds__(256, 1)
void gemm_mma(const __half* __restrict__ A, const __half* __restrict__ Bt,
              const float* __restrict__ bias, void* __restrict__ Cout,
              int M, int K, int N)
{
    extern __shared__ char smc[];
    const uint32_t sbase = smem_u32(smc);
    const int tid = threadIdx.x;
    const int wid = tid >> 5, lane = tid & 31;
    const int g = lane >> 2, tq = lane & 3;
    const int wm = wid >> 2, wn = wid & 3;
    const int row0 = blockIdx.y * BM;
    const int col0 = blockIdx.x * BN;

    const int lm = lane >> 3, lr = lane & 7;
    const uint32_t aoff = (uint32_t)((wm * 64 + (lm & 1) * 8 + lr) * ROWB + ((lm >> 1) * 8) * 2);
    const uint32_t boff = (uint32_t)(BM * ROWB + (wn * 64 + (lm >> 1) * 8 + lr) * ROWB + ((lm & 1) * 8) * 2);

    float acc[4][8][4];
    #pragma unroll
    for (int i = 0; i < 4; i++)
        #pragma unroll
        for (int j = 0; j < 8; j++)
            #pragma unroll
            for (int r = 0; r < 4; r++) acc[i][j][r] = 0.f;

    const int nchunk = K >> 6;

    auto issue = [&](int c) {
        const uint32_t st = sbase + (c % 3) * STAGEB;
        const int k0 = c << 6;
        #pragma unroll
        for (int i = 0; i < 4; i++) {          // A: 1024 segs of 16B
            const int seg = tid + i * 256;
            const int r = seg >> 3, c8 = seg & 7;
            const uint32_t da = st + r * ROWB + c8 * 16;
            const __half* sa = A + (size_t)(row0 + r) * K + k0 + c8 * 8;
            const int pn = (row0 + r < M) ? 16 : 0;
            asm volatile("cp.async.ca.shared.global [%0], [%1], 16, %2;"
                         :: "r"(da), "l"(sa), "r"(pn));
        }
        #pragma unroll
        for (int i = 0; i < 8; i++) {          // B: 2048 segs
            const int seg = tid + i * 256;
            const int r = seg >> 3, c8 = seg & 7;
            const uint32_t db = st + BM * ROWB + r * ROWB + c8 * 16;
            const __half* sb = Bt + (size_t)(col0 + r) * K + k0 + c8 * 8;
            asm volatile("cp.async.ca.shared.global [%0], [%1], 16;" :: "r"(db), "l"(sb));
        }
        asm volatile("cp.async.commit_group;");
    };

    issue(0);
    if (nchunk > 1) issue(1);

    for (int c = 0; c < nchunk; c++) {
        if (c + 1 < nchunk) asm volatile("cp.async.wait_group 1;");
        else                asm volatile("cp.async.wait_group 0;");
        __syncthreads();
        if (c + 2 < nchunk) issue(c + 2);

        const uint32_t abase = sbase + (c % 3) * STAGEB + aoff;
        const uint32_t bbase = sbase + (c % 3) * STAGEB + boff;
        #pragma unroll
        for (int ks = 0; ks < 4; ks++) {
            uint32_t a[4][4], b[4][4];
            #pragma unroll
            for (int fm = 0; fm < 4; fm++)
                LDSM4(a[fm], abase + fm * (16 * ROWB) + ks * 32);
            #pragma unroll
            for (int fp = 0; fp < 4; fp++)
                LDSM4(b[fp], bbase + fp * (16 * ROWB) + ks * 32);
            #pragma unroll
            for (int fm = 0; fm < 4; fm++)
                #pragma unroll
                for (int fn = 0; fn < 8; fn++)
                    mma_f16(acc[fm][fn], a[fm], b[fn >> 1][(fn & 1) * 2], b[fn >> 1][(fn & 1) * 2 + 1]);
        }
        // no trailing barrier: next iteration's top barrier orders stage reuse
    }

    #pragma unroll
    for (int fm = 0; fm < 4; fm++) {
        const int r0 = row0 + wm * 64 + fm * 16 + g;
        #pragma unroll
        for (int fn = 0; fn < 8; fn++) {
            const int cc = col0 + wn * 64 + fn * 8 + tq * 2;
            const float2 bv = *(const float2*)(bias + cc);
            #pragma unroll
            for (int half = 0; half < 2; half++) {
                const int rr = r0 + half * 8;
                if (rr < M) {
                    const float ox = fmaxf(acc[fm][fn][half * 2 + 0] + bv.x, 0.f);
                    const float oy = fmaxf(acc[fm][fn][half * 2 + 1] + bv.y, 0.f);
                    if (FP32OUT) {
                        float2 o; o.x = ox; o.y = oy;
                        *(float2*)((float*)Cout + (size_t)rr * N + cc) = o;
                    } else {
                        *(uint32_t*)((__half*)Cout + (size_t)rr * N + cc) = pack_h2(ox, oy);
                    }
                }
            }
        }
    }
}

// ---------------- fused per-graph mean pool + head (batch is sorted) ----------------
__device__ __forceinline__ int dev_lower_bound(const int* a, int n, int v) {
    int lo = 0, hi = n;
    while (lo < hi) { int m = (lo + hi) >> 1; if (a[m] < v) lo = m + 1; else hi = m; }
    return lo;
}

__global__ void poolhead_kernel(const float* __restrict__ h, const int* __restrict__ batch,
                                const float* __restrict__ dw, const float* __restrict__ db,
                                float* __restrict__ out)
{
    const int g = blockIdx.x;
    const int t = threadIdx.x;  // 256
    const int lo = dev_lower_bound(batch, NN, g);
    const int hi = dev_lower_bound(batch, NN, g + 1);
    float a0 = 0.f, a1 = 0.f, a2 = 0.f;
    int r = lo;
    for (; r + 2 <= hi; r += 2) {
        const float* r0 = h + (size_t)r * EMB;
        const float* r1 = h + (size_t)(r + 1) * EMB;
        a0 += r0[t] + r1[t];
        a1 += r0[t + 256] + r1[t + 256];
        a2 += r0[t + 512] + r1[t + 512];
    }
    if (r < hi) {
        const float* row = h + (size_t)r * EMB;
        a0 += row[t]; a1 += row[t + 256]; a2 += row[t + 512];
    }
    const float inv = 1.0f / fmaxf((float)(hi - lo), 1.0f);
    __shared__ float sp[EMB];
    sp[t] = a0 * inv; sp[t + 256] = a1 * inv; sp[t + 512] = a2 * inv;
    __syncthreads();

    float p0 = 0.f, p1 = 0.f, p2 = 0.f, p3 = 0.f;
    #pragma unroll
    for (int kk = t; kk < EMB; kk += 256) {
        const float pv = sp[kk];
        const float4 w = *(const float4*)(dw + kk * 4);
        p0 = fmaf(pv, w.x, p0); p1 = fmaf(pv, w.y, p1);
        p2 = fmaf(pv, w.z, p2); p3 = fmaf(pv, w.w, p3);
    }
    #pragma unroll
    for (int d = 16; d >= 1; d >>= 1) {
        p0 += __shfl_xor_sync(~0u, p0, d);
        p1 += __shfl_xor_sync(~0u, p1, d);
        p2 += __shfl_xor_sync(~0u, p2, d);
        p3 += __shfl_xor_sync(~0u, p3, d);
    }
    __shared__ float red[4][8];
    const int w8 = t >> 5;
    if ((t & 31) == 0) { red[0][w8] = p0; red[1][w8] = p1; red[2][w8] = p2; red[3][w8] = p3; }
    __syncthreads();
    if (t == 0) {
        float l[4];
        #pragma unroll
        for (int i = 0; i < 4; i++) {
            float s = 0.f;
            #pragma unroll
            for (int j = 0; j < 8; j++) s += red[i][j];
            l[i] = s + db[i];
        }
        const float m = fmaxf(fmaxf(l[0], l[1]), fmaxf(l[2], l[3]));
        const float lse = logf(expf(l[0] - m) + expf(l[1] - m) + expf(l[2] - m) + expf(l[3] - m)) + m;
        float* o = out + g * 4;
        o[0] = l[0] - lse; o[1] = l[1] - lse; o[2] = l[2] - lse; o[3] = l[3] - lse;
    }
}

// ---------------- launch ----------------
extern "C" void kernel_launch(void* const* d_in, const int* in_sizes, int n_in,
                              void* d_out, int out_size)
{
    const float* x        = (const float*)d_in[0];
    const int*   ei       = (const int*)d_in[1];
    const int*   batch    = (const int*)d_in[2];
    const float* conv0_w  = (const float*)d_in[3];
    const float* bn0_g    = (const float*)d_in[4];
    const float* bn0_b    = (const float*)d_in[5];
    const float* bn0_m    = (const float*)d_in[6];
    const float* bn0_v    = (const float*)d_in[7];
    const float* conv1_w  = (const float*)d_in[8];
    const float* conv2_w  = (const float*)d_in[9];
    const float* bn2_g    = (const float*)d_in[10];
    const float* bn2_b    = (const float*)d_in[11];
    const float* bn2_m    = (const float*)d_in[12];
    const float* bn2_v    = (const float*)d_in[13];
    const float* g1w1     = (const float*)d_in[14];
    const float* g1b1     = (const float*)d_in[15];
    const float* g1w2     = (const float*)d_in[16];
    const float* g1b2     = (const float*)d_in[17];
    const float* g2w1     = (const float*)d_in[18];
    const float* g2b1     = (const float*)d_in[19];
    const float* g2w2     = (const float*)d_in[20];
    const float* g2b2     = (const float*)d_in[21];
    const float* dense_w  = (const float*)d_in[22];
    const float* dense_b  = (const float*)d_in[23];
    float* out = (float*)d_out;

    float *h0f, *aggf, *zf, *h1f, *wt1f, *wt2f, *wt3f, *wt4f;
    int *deg, *off, *srcs;
    cudaGetSymbolAddress((void**)&h0f,    g_h0);
    cudaGetSymbolAddress((void**)&aggf,   g_agg);
    cudaGetSymbolAddress((void**)&zf,     g_z);
    cudaGetSymbolAddress((void**)&h1f,    g_h1);
    cudaGetSymbolAddress((void**)&wt1f,   g_wt1);
    cudaGetSymbolAddress((void**)&wt2f,   g_wt2);
    cudaGetSymbolAddress((void**)&wt3f,   g_wt3);
    cudaGetSymbolAddress((void**)&wt4f,   g_wt4);
    cudaGetSymbolAddress((void**)&deg,    g_deg);
    cudaGetSymbolAddress((void**)&off,    g_off);
    cudaGetSymbolAddress((void**)&srcs,   g_srcs);

    __half* h0  = (__half*)h0f;
    __half* agg = (__half*)aggf;
    __half* z   = (__half*)zf;
    __half* h1  = (__half*)h1f;
    float*  h2  = h1f;             // fp32 view for gemm4 output
    __half* wt1 = (__half*)wt1f;
    __half* wt2 = (__half*)wt2f;
    __half* wt3 = (__half*)wt3f;
    __half* wt4 = (__half*)wt4f;

    cudaFuncSetAttribute(gemm_mma<false>, cudaFuncAttributeMaxDynamicSharedMemorySize, GEMM_SMEM);
    cudaFuncSetAttribute(gemm_mma<true >, cudaFuncAttributeMaxDynamicSharedMemorySize, GEMM_SMEM);

    static cudaStream_t s_sort = nullptr, s_wt = nullptr;
    static cudaEvent_t  e_root = nullptr, e_sort = nullptr, e_wt = nullptr;
    if (!s_sort) {
        cudaStreamCreateWithFlags(&s_sort, cudaStreamNonBlocking);
        cudaStreamCreateWithFlags(&s_wt,   cudaStreamNonBlocking);
        cudaEventCreateWithFlags(&e_root, cudaEventDisableTiming);
        cudaEventCreateWithFlags(&e_sort, cudaEventDisableTiming);
        cudaEventCreateWithFlags(&e_wt,   cudaEventDisableTiming);
    }

    const dim3 ggrid(EMB / BN, (NN + BM - 1) / BM);   // (3, 157)

    cudaEventRecord(e_root, 0);
    cudaStreamWaitEvent(s_sort, e_root, 0);
    cudaStreamWaitEvent(s_wt,   e_root, 0);

    // side stream 1: edge sort chain
    zero_deg_kernel<<<(NN_PAD + 255) / 256, 256, 0, s_sort>>>(deg);
    hist_kernel<<<(EE + 255) / 256, 256, 0, s_sort>>>(ei, deg);
    scan_kernel<<<1, 1024, 0, s_sort>>>(deg, off);
    fill_kernel<<<(EE + 255) / 256, 256, 0, s_sort>>>(ei, off, deg, srcs);
    cudaEventRecord(e_sort, s_sort);

    // side stream 2: weight transposes
    transpose_all_kernel<<<dim3(EMB / 32, EMB / 32, 4), dim3(32, 8), 0, s_wt>>>(
        g1w1, g1w2, g2w1, g2w2, wt1, wt2, wt3, wt4);
    cudaEventRecord(e_wt, s_wt);

    // main stream: conv overlaps both side chains
    conv_kernel<<<NN, 256>>>(x, conv0_w, bn0_g, bn0_b, bn0_m, bn0_v,
                             conv1_w, conv2_w, bn2_g, bn2_b, bn2_m, bn2_v, h0);

    cudaStreamWaitEvent(0, e_sort, 0);
    cudaStreamWaitEvent(0, e_wt, 0);

    // GIN1
    gather_kernel<FIN><<<NN, FIN / 8>>>(h0, off, srcs, agg);
    gemm_mma<false><<<ggrid, 256, GEMM_SMEM>>>(agg, wt1, g1b1, z,  NN, FIN, EMB);
    gemm_mma<false><<<ggrid, 256, GEMM_SMEM>>>(z,   wt2, g1b2, h1, NN, EMB, EMB);
    // GIN2
    gather_kernel<EMB><<<NN, EMB / 8>>>(h1, off, srcs, agg);
    gemm_mma<false><<<ggrid, 256, GEMM_SMEM>>>(agg, wt3, g2b1, z,  NN, EMB, EMB);
    gemm_mma<true ><<<ggrid, 256, GEMM_SMEM>>>(z,   wt4, g2b2, h2, NN, EMB, EMB);
    // fused pool + head
    poolhead_kernel<<<GG, 256>>>(h2, batch, dense_w, dense_b, out);
}